// round 1
// baseline (speedup 1.0000x reference)
#include <cuda_runtime.h>
#include <math.h>

// Problem shape (fixed by the reference setup_inputs).
static constexpr int BATCH = 8;
static constexpr int NQ = 2048;
static constexpr int NK = 2048;
static constexpr int DH = 512;

// 128 MiB scratch for the materialized score/prob matrix S[B, NQ, NK].
// __device__ global array: allowed (no cudaMalloc anywhere).
__device__ float g_S[(size_t)BATCH * NQ * NK];

#define BM 128
#define BN 128
#define BKK 16
#define TM 8
#define TN 8

// ---------------------------------------------------------------------------
// C[M,N] = A[M,K] * B[N,K]^T   (A, B row-major with K contiguous) — QK^T
// ---------------------------------------------------------------------------
__global__ __launch_bounds__(256, 2)
void gemm_nt_kernel(const float* __restrict__ A, const float* __restrict__ B,
                    float* __restrict__ C, int M, int N, int K) {
    __shared__ float As[BKK][BM];
    __shared__ float Bs[BKK][BN];
    const int b = blockIdx.z;
    A += (size_t)b * M * K;
    B += (size_t)b * N * K;
    C += (size_t)b * M * N;
    const int tid = threadIdx.x;
    const int m0 = blockIdx.y * BM;
    const int n0 = blockIdx.x * BN;
    const int rm = (tid >> 4) * TM;
    const int rn = (tid & 15) * TN;

    const int row0 = tid >> 2;        // 0..63
    const int kc   = (tid & 3) * 4;   // 0,4,8,12

    const float* Ap0 = A + (size_t)(m0 + row0) * K + kc;
    const float* Ap1 = A + (size_t)(m0 + row0 + 64) * K + kc;
    const float* Bp0 = B + (size_t)(n0 + row0) * K + kc;
    const float* Bp1 = B + (size_t)(n0 + row0 + 64) * K + kc;

    float4 ra0 = *(const float4*)(Ap0);
    float4 ra1 = *(const float4*)(Ap1);
    float4 rb0 = *(const float4*)(Bp0);
    float4 rb1 = *(const float4*)(Bp1);

    float acc[TM][TN] = {};

    for (int k0 = 0; k0 < K; k0 += BKK) {
        As[kc + 0][row0] = ra0.x; As[kc + 1][row0] = ra0.y;
        As[kc + 2][row0] = ra0.z; As[kc + 3][row0] = ra0.w;
        As[kc + 0][row0 + 64] = ra1.x; As[kc + 1][row0 + 64] = ra1.y;
        As[kc + 2][row0 + 64] = ra1.z; As[kc + 3][row0 + 64] = ra1.w;
        Bs[kc + 0][row0] = rb0.x; Bs[kc + 1][row0] = rb0.y;
        Bs[kc + 2][row0] = rb0.z; Bs[kc + 3][row0] = rb0.w;
        Bs[kc + 0][row0 + 64] = rb1.x; Bs[kc + 1][row0 + 64] = rb1.y;
        Bs[kc + 2][row0 + 64] = rb1.z; Bs[kc + 3][row0 + 64] = rb1.w;
        __syncthreads();

        if (k0 + BKK < K) {  // register prefetch of next K-slab
            ra0 = *(const float4*)(Ap0 + k0 + BKK);
            ra1 = *(const float4*)(Ap1 + k0 + BKK);
            rb0 = *(const float4*)(Bp0 + k0 + BKK);
            rb1 = *(const float4*)(Bp1 + k0 + BKK);
        }

        #pragma unroll
        for (int k = 0; k < BKK; k++) {
            float4 a0 = *(const float4*)&As[k][rm];
            float4 a1 = *(const float4*)&As[k][rm + 4];
            float4 b0 = *(const float4*)&Bs[k][rn];
            float4 b1 = *(const float4*)&Bs[k][rn + 4];
            float af[TM] = {a0.x, a0.y, a0.z, a0.w, a1.x, a1.y, a1.z, a1.w};
            float bf[TN] = {b0.x, b0.y, b0.z, b0.w, b1.x, b1.y, b1.z, b1.w};
            #pragma unroll
            for (int i = 0; i < TM; i++)
                #pragma unroll
                for (int j = 0; j < TN; j++)
                    acc[i][j] = fmaf(af[i], bf[j], acc[i][j]);
        }
        __syncthreads();
    }

    #pragma unroll
    for (int i = 0; i < TM; i++) {
        float* Cr = C + (size_t)(m0 + rm + i) * N + n0 + rn;
        *(float4*)(Cr)     = make_float4(acc[i][0], acc[i][1], acc[i][2], acc[i][3]);
        *(float4*)(Cr + 4) = make_float4(acc[i][4], acc[i][5], acc[i][6], acc[i][7]);
    }
}

// ---------------------------------------------------------------------------
// C[M,N] = A[M,K] * B[K,N]   (all row-major) — P·K
// ---------------------------------------------------------------------------
__global__ __launch_bounds__(256, 2)
void gemm_nn_kernel(const float* __restrict__ A, const float* __restrict__ B,
                    float* __restrict__ C, int M, int N, int K) {
    __shared__ float As[BKK][BM];
    __shared__ float Bs[BKK][BN];
    const int b = blockIdx.z;
    A += (size_t)b * M * K;
    B += (size_t)b * K * N;
    C += (size_t)b * M * N;
    const int tid = threadIdx.x;
    const int m0 = blockIdx.y * BM;
    const int n0 = blockIdx.x * BN;
    const int rm = (tid >> 4) * TM;
    const int rn = (tid & 15) * TN;

    const int arow = tid >> 2;         // 0..63
    const int akc  = (tid & 3) * 4;    // 0,4,8,12
    const int bkr  = tid >> 5;         // 0..7
    const int bnc  = (tid & 31) * 4;   // 0..124

    const float* Ap0 = A + (size_t)(m0 + arow) * K + akc;
    const float* Ap1 = Ap0 + (size_t)64 * K;
    const float* Bp0 = B + (size_t)bkr * N + n0 + bnc;
    const float* Bp1 = Bp0 + (size_t)8 * N;

    float4 ra0 = *(const float4*)(Ap0);
    float4 ra1 = *(const float4*)(Ap1);
    float4 rb0 = *(const float4*)(Bp0);
    float4 rb1 = *(const float4*)(Bp1);

    float acc[TM][TN] = {};

    for (int k0 = 0; k0 < K; k0 += BKK) {
        As[akc + 0][arow] = ra0.x; As[akc + 1][arow] = ra0.y;
        As[akc + 2][arow] = ra0.z; As[akc + 3][arow] = ra0.w;
        As[akc + 0][arow + 64] = ra1.x; As[akc + 1][arow + 64] = ra1.y;
        As[akc + 2][arow + 64] = ra1.z; As[akc + 3][arow + 64] = ra1.w;
        *(float4*)&Bs[bkr][bnc]     = rb0;
        *(float4*)&Bs[bkr + 8][bnc] = rb1;
        __syncthreads();

        if (k0 + BKK < K) {
            ra0 = *(const float4*)(Ap0 + k0 + BKK);
            ra1 = *(const float4*)(Ap1 + k0 + BKK);
            rb0 = *(const float4*)(Bp0 + (size_t)(k0 + BKK) * N);
            rb1 = *(const float4*)(Bp1 + (size_t)(k0 + BKK) * N);
        }

        #pragma unroll
        for (int k = 0; k < BKK; k++) {
            float4 a0 = *(const float4*)&As[k][rm];
            float4 a1 = *(const float4*)&As[k][rm + 4];
            float4 b0 = *(const float4*)&Bs[k][rn];
            float4 b1 = *(const float4*)&Bs[k][rn + 4];
            float af[TM] = {a0.x, a0.y, a0.z, a0.w, a1.x, a1.y, a1.z, a1.w};
            float bf[TN] = {b0.x, b0.y, b0.z, b0.w, b1.x, b1.y, b1.z, b1.w};
            #pragma unroll
            for (int i = 0; i < TM; i++)
                #pragma unroll
                for (int j = 0; j < TN; j++)
                    acc[i][j] = fmaf(af[i], bf[j], acc[i][j]);
        }
        __syncthreads();
    }

    #pragma unroll
    for (int i = 0; i < TM; i++) {
        float* Cr = C + (size_t)(m0 + rm + i) * N + n0 + rn;
        *(float4*)(Cr)     = make_float4(acc[i][0], acc[i][1], acc[i][2], acc[i][3]);
        *(float4*)(Cr + 4) = make_float4(acc[i][4], acc[i][5], acc[i][6], acc[i][7]);
    }
}

// ---------------------------------------------------------------------------
// Row softmax over NK=2048, in place. One block (256 threads) per row.
// ---------------------------------------------------------------------------
__global__ __launch_bounds__(256)
void softmax_kernel(float* __restrict__ S) {
    float* row = S + (size_t)blockIdx.x * NK;
    const int tid = threadIdx.x;

    float4 v0 = *(const float4*)(row + (size_t)tid * 4);
    float4 v1 = *(const float4*)(row + (size_t)(tid + 256) * 4);

    float mx = fmaxf(fmaxf(fmaxf(v0.x, v0.y), fmaxf(v0.z, v0.w)),
                     fmaxf(fmaxf(v1.x, v1.y), fmaxf(v1.z, v1.w)));

    __shared__ float shm[8];
    __shared__ float shs[8];

    #pragma unroll
    for (int o = 16; o; o >>= 1) mx = fmaxf(mx, __shfl_xor_sync(0xffffffffu, mx, o));
    if ((tid & 31) == 0) shm[tid >> 5] = mx;
    __syncthreads();
    mx = shm[0];
    #pragma unroll
    for (int i = 1; i < 8; i++) mx = fmaxf(mx, shm[i]);

    v0.x = expf(v0.x - mx); v0.y = expf(v0.y - mx);
    v0.z = expf(v0.z - mx); v0.w = expf(v0.w - mx);
    v1.x = expf(v1.x - mx); v1.y = expf(v1.y - mx);
    v1.z = expf(v1.z - mx); v1.w = expf(v1.w - mx);

    float s = v0.x + v0.y + v0.z + v0.w + v1.x + v1.y + v1.z + v1.w;
    #pragma unroll
    for (int o = 16; o; o >>= 1) s += __shfl_xor_sync(0xffffffffu, s, o);
    if ((tid & 31) == 0) shs[tid >> 5] = s;
    __syncthreads();
    s = 0.0f;
    #pragma unroll
    for (int i = 0; i < 8; i++) s += shs[i];

    const float inv = 1.0f / s;
    v0.x *= inv; v0.y *= inv; v0.z *= inv; v0.w *= inv;
    v1.x *= inv; v1.y *= inv; v1.z *= inv; v1.w *= inv;

    *(float4*)(row + (size_t)tid * 4)         = v0;
    *(float4*)(row + (size_t)(tid + 256) * 4) = v1;
}

// ---------------------------------------------------------------------------
extern "C" void kernel_launch(void* const* d_in, const int* in_sizes, int n_in,
                              void* d_out, int out_size) {
    const float* Q  = (const float*)d_in[0];  // [B, NQ, DH]
    const float* Kp = (const float*)d_in[1];  // [B, NK, DH]
    float* O = (float*)d_out;                 // [B, NQ, DH]

    float* S = nullptr;
    cudaGetSymbolAddress((void**)&S, g_S);    // not a stream op; capture-safe

    dim3 blk(256);
    // S = Q K^T
    gemm_nt_kernel<<<dim3(NK / BN, NQ / BM, BATCH), blk>>>(Q, Kp, S, NQ, NK, DH);
    // P = softmax_rows(S), in place
    softmax_kernel<<<BATCH * NQ, blk>>>(S);
    // O = P K
    gemm_nn_kernel<<<dim3(DH / BN, NQ / BM, BATCH), blk>>>(S, Kp, O, NQ, DH, NK);
}

// round 8
// speedup vs baseline: 1.8490x; 1.8490x over previous
#include <cuda_runtime.h>
#include <cuda_bf16.h>
#include <math.h>
#include <cstdint>

static constexpr int BATCH = 8;
static constexpr int NQ = 2048;
static constexpr int NK = 2048;
static constexpr int DH = 512;

// ---------------- device scratch (no allocs allowed) ----------------
__device__ float g_S[(size_t)BATCH * NQ * NK];                      // 128 MiB
__device__ __nv_bfloat16 g_Qhi[(size_t)BATCH * NQ * DH];
__device__ __nv_bfloat16 g_Qlo[(size_t)BATCH * NQ * DH];
__device__ __nv_bfloat16 g_Khi[(size_t)BATCH * NK * DH];
__device__ __nv_bfloat16 g_Klo[(size_t)BATCH * NK * DH];
__device__ __nv_bfloat16 g_Kthi[(size_t)BATCH * DH * NK];           // K^T [B, DH, NK]
__device__ __nv_bfloat16 g_Ktlo[(size_t)BATCH * DH * NK];
__device__ __nv_bfloat16 g_Phi[(size_t)BATCH * NQ * NK];            // 64 MiB
__device__ __nv_bfloat16 g_Plo[(size_t)BATCH * NQ * NK];

// ---------------- helpers (sm_80-era PTX only: safe on compute_103) --------
__device__ __forceinline__ uint32_t smem_u32(const void* p) {
    uint32_t a;
    asm("{ .reg .u64 t; cvta.to.shared.u64 t, %1; cvt.u32.u64 %0, t; }" : "=r"(a) : "l"(p));
    return a;
}
__device__ __forceinline__ void cpa16(uint32_t dst, const void* src) {
    asm volatile("cp.async.cg.shared.global [%0], [%1], 16;" :: "r"(dst), "l"(src));
}
__device__ __forceinline__ void cpa_commit() { asm volatile("cp.async.commit_group;" ::: "memory"); }
__device__ __forceinline__ void cpa_wait1()  { asm volatile("cp.async.wait_group 1;" ::: "memory"); }

#define LDSM4(r, addr) \
    asm volatile("ldmatrix.sync.aligned.m8n8.x4.shared.b16 {%0,%1,%2,%3}, [%4];" \
                 : "=r"((r)[0]), "=r"((r)[1]), "=r"((r)[2]), "=r"((r)[3]) : "r"(addr))

#define MMA16816(d, a, b0v, b1v) \
    asm volatile("mma.sync.aligned.m16n8k16.row.col.f32.bf16.bf16.f32 " \
                 "{%0,%1,%2,%3}, {%4,%5,%6,%7}, {%8,%9}, {%0,%1,%2,%3};" \
                 : "+f"((d)[0]), "+f"((d)[1]), "+f"((d)[2]), "+f"((d)[3]) \
                 : "r"((a)[0]), "r"((a)[1]), "r"((a)[2]), "r"((a)[3]), \
                   "r"(b0v), "r"(b1v))

// ---------------------------------------------------------------------------
// Split-bf16 GEMM via mma.sync (HMMA): C[M,N] = (Ahi+Alo) * (Bhi+Blo)^T
// A row-major [M,K] (K contig), B row-major [N,K] (K contig), fp32 out.
// Emulation: hi*hi + lo*hi + hi*lo as a virtual K loop over 3 phases.
// One 128x128 tile per CTA, 256 threads, BK=32, cp.async double buffer.
// SMEM rows padded to 80B (64B data + 16B) -> conflict-free ldmatrix.
// ---------------------------------------------------------------------------
static constexpr int ROWB = 80;                   // bytes per smem row
static constexpr int BTILE = 128 * ROWB;          // 10240 B per operand tile
static constexpr int STAGE = 2 * BTILE;           // A + B per stage
static constexpr int GEMM_SMEM = 2 * STAGE;       // 40960 B

__global__ __launch_bounds__(256, 2)
void gemm_mma_kernel(const __nv_bfloat16* __restrict__ Ahi, const __nv_bfloat16* __restrict__ Alo,
                     const __nv_bfloat16* __restrict__ Bhi, const __nv_bfloat16* __restrict__ Blo,
                     float* __restrict__ C, int M, int N, int K)
{
    extern __shared__ char smem[];
    const uint32_t sb = smem_u32(smem);
    const int tid = threadIdx.x;
    const int warp = tid >> 5, lane = tid & 31;
    const int wm = warp >> 2, wn = warp & 3;       // 2 x 4 warp grid
    const int bz = blockIdx.z;
    const int m0 = blockIdx.y * 128, n0 = blockIdx.x * 128;

    const size_t offA = (size_t)bz * M * K + (size_t)m0 * K;
    const size_t offB = (size_t)bz * N * K + (size_t)n0 * K;
    const __nv_bfloat16* Ap[3] = {Ahi + offA, Alo + offA, Ahi + offA};
    const __nv_bfloat16* Bp[3] = {Bhi + offB, Bhi + offB, Blo + offB};

    const int KC = K / 32;         // real-K chunks
    const int NC = 3 * KC;         // virtual chunks (3 split phases)

    const int lr = tid >> 2;       // 0..63  (load row)
    const int ls = tid & 3;        // 0..3   (16B chunk in row)

    auto load_chunk = [&](int c, uint32_t buf) {
        const int ph = c / KC;
        const int kk = (c - ph * KC) * 32;
        const char* ga = (const char*)Ap[ph] + (size_t)kk * 2;
        const char* gb = (const char*)Bp[ph] + (size_t)kk * 2;
        cpa16(buf + lr * ROWB + ls * 16,                 ga + (size_t)lr * K * 2 + ls * 16);
        cpa16(buf + (lr + 64) * ROWB + ls * 16,          ga + (size_t)(lr + 64) * K * 2 + ls * 16);
        cpa16(buf + BTILE + lr * ROWB + ls * 16,         gb + (size_t)lr * K * 2 + ls * 16);
        cpa16(buf + BTILE + (lr + 64) * ROWB + ls * 16,  gb + (size_t)(lr + 64) * K * 2 + ls * 16);
    };

    load_chunk(0, sb);          cpa_commit();
    load_chunk(1, sb + STAGE);  cpa_commit();

    float acc[4][4][4];
    #pragma unroll
    for (int i = 0; i < 4; i++)
        #pragma unroll
        for (int j = 0; j < 4; j++)
            #pragma unroll
            for (int r = 0; r < 4; r++) acc[i][j][r] = 0.0f;

    // ldmatrix base addresses (per-warp, per-lane): row = (lane&15), +16B for k-half
    const uint32_t aoff = (uint32_t)((wm * 64 + (lane & 15)) * ROWB + (lane >> 4) * 16);
    const uint32_t boff = (uint32_t)(BTILE + (wn * 32 + (lane & 15)) * ROWB + (lane >> 4) * 16);

    for (int c = 0; c < NC; c++) {
        const uint32_t bp = sb + (uint32_t)(c & 1) * STAGE;
        cpa_wait1();
        __syncthreads();

        #pragma unroll
        for (int ks = 0; ks < 2; ks++) {
            uint32_t a[4][4];
            #pragma unroll
            for (int mi = 0; mi < 4; mi++)
                LDSM4(a[mi], bp + aoff + mi * 16 * ROWB + ks * 32);
            uint32_t b[2][4];
            #pragma unroll
            for (int nb = 0; nb < 2; nb++)
                LDSM4(b[nb], bp + boff + nb * 16 * ROWB + ks * 32);
            #pragma unroll
            for (int mi = 0; mi < 4; mi++) {
                #pragma unroll
                for (int nb = 0; nb < 2; nb++) {
                    MMA16816(acc[mi][nb * 2 + 0], a[mi], b[nb][0], b[nb][2]);
                    MMA16816(acc[mi][nb * 2 + 1], a[mi], b[nb][1], b[nb][3]);
                }
            }
        }

        __syncthreads();
        if (c + 2 < NC) load_chunk(c + 2, bp);
        cpa_commit();
    }

    // Epilogue: fragment layout m16n8: c0,c1 @ (row, 2*(lane%4)); c2,c3 @ row+8
    float* pC = C + (size_t)bz * M * N + (size_t)(m0 + wm * 64) * N + n0 + wn * 32;
    const int er = lane >> 2, ec = (lane & 3) * 2;
    #pragma unroll
    for (int mi = 0; mi < 4; mi++) {
        #pragma unroll
        for (int ni = 0; ni < 4; ni++) {
            float* d0 = pC + (size_t)(mi * 16 + er) * N + ni * 8 + ec;
            float* d1 = d0 + (size_t)8 * N;
            *(float2*)d0 = make_float2(acc[mi][ni][0], acc[mi][ni][1]);
            *(float2*)d1 = make_float2(acc[mi][ni][2], acc[mi][ni][3]);
        }
    }
}

// ---------------------------------------------------------------------------
// fp32 -> (bf16 hi, bf16 lo) elementwise split; 4 elems/thread
// ---------------------------------------------------------------------------
__global__ __launch_bounds__(256)
void split_kernel(const float* __restrict__ x, __nv_bfloat16* __restrict__ hi,
                  __nv_bfloat16* __restrict__ lo) {
    const size_t i = ((size_t)blockIdx.x * 256 + threadIdx.x) * 4;
    const float4 v = *(const float4*)(x + i);
    __nv_bfloat162 h0, h1, l0, l1;
    h0.x = __float2bfloat16(v.x); h0.y = __float2bfloat16(v.y);
    h1.x = __float2bfloat16(v.z); h1.y = __float2bfloat16(v.w);
    l0.x = __float2bfloat16(v.x - __bfloat162float(h0.x));
    l0.y = __float2bfloat16(v.y - __bfloat162float(h0.y));
    l1.x = __float2bfloat16(v.z - __bfloat162float(h1.x));
    l1.y = __float2bfloat16(v.w - __bfloat162float(h1.y));
    ((__nv_bfloat162*)(hi + i))[0] = h0; ((__nv_bfloat162*)(hi + i))[1] = h1;
    ((__nv_bfloat162*)(lo + i))[0] = l0; ((__nv_bfloat162*)(lo + i))[1] = l1;
}

// ---------------------------------------------------------------------------
// K [B, NK, DH] fp32 -> transposed splits [B, DH, NK] bf16 hi/lo
// ---------------------------------------------------------------------------
__global__ __launch_bounds__(256)
void transpose_split_kernel(const float* __restrict__ Kin,
                            __nv_bfloat16* __restrict__ Thi,
                            __nv_bfloat16* __restrict__ Tlo) {
    __shared__ float tile[32][33];
    const int b = blockIdx.z;
    const int n0 = blockIdx.x * 32, d0 = blockIdx.y * 32;
    const int tx = threadIdx.x, ty = threadIdx.y;   // (32, 8)
    const float* src = Kin + (size_t)b * NK * DH;
    #pragma unroll
    for (int j = 0; j < 32; j += 8)
        tile[ty + j][tx] = src[(size_t)(n0 + ty + j) * DH + d0 + tx];
    __syncthreads();
    __nv_bfloat16* th = Thi + (size_t)b * DH * NK;
    __nv_bfloat16* tl = Tlo + (size_t)b * DH * NK;
    #pragma unroll
    for (int j = 0; j < 32; j += 8) {
        const float v = tile[tx][ty + j];
        const __nv_bfloat16 h = __float2bfloat16(v);
        th[(size_t)(d0 + ty + j) * NK + n0 + tx] = h;
        tl[(size_t)(d0 + ty + j) * NK + n0 + tx] = __float2bfloat16(v - __bfloat162float(h));
    }
}

// ---------------------------------------------------------------------------
// Row softmax over NK, emitting split-bf16 probabilities.
// ---------------------------------------------------------------------------
__device__ __forceinline__ void store_split2(__nv_bfloat162* ph, __nv_bfloat162* pl,
                                             float a, float b) {
    __nv_bfloat162 h, l;
    h.x = __float2bfloat16(a); h.y = __float2bfloat16(b);
    l.x = __float2bfloat16(a - __bfloat162float(h.x));
    l.y = __float2bfloat16(b - __bfloat162float(h.y));
    *ph = h; *pl = l;
}

__global__ __launch_bounds__(256)
void softmax_split_kernel(const float* __restrict__ S,
                          __nv_bfloat16* __restrict__ Phi,
                          __nv_bfloat16* __restrict__ Plo) {
    const float* row = S + (size_t)blockIdx.x * NK;
    __nv_bfloat162* ph = (__nv_bfloat162*)(Phi + (size_t)blockIdx.x * NK);
    __nv_bfloat162* pl = (__nv_bfloat162*)(Plo + (size_t)blockIdx.x * NK);
    const int tid = threadIdx.x;

    float4 v0 = *(const float4*)(row + (size_t)tid * 4);
    float4 v1 = *(const float4*)(row + (size_t)(tid + 256) * 4);

    float mx = fmaxf(fmaxf(fmaxf(v0.x, v0.y), fmaxf(v0.z, v0.w)),
                     fmaxf(fmaxf(v1.x, v1.y), fmaxf(v1.z, v1.w)));

    __shared__ float shm[8];
    __shared__ float shs[8];

    #pragma unroll
    for (int o = 16; o; o >>= 1) mx = fmaxf(mx, __shfl_xor_sync(0xffffffffu, mx, o));
    if ((tid & 31) == 0) shm[tid >> 5] = mx;
    __syncthreads();
    mx = shm[0];
    #pragma unroll
    for (int i = 1; i < 8; i++) mx = fmaxf(mx, shm[i]);

    v0.x = expf(v0.x - mx); v0.y = expf(v0.y - mx);
    v0.z = expf(v0.z - mx); v0.w = expf(v0.w - mx);
    v1.x = expf(v1.x - mx); v1.y = expf(v1.y - mx);
    v1.z = expf(v1.z - mx); v1.w = expf(v1.w - mx);

    float s = v0.x + v0.y + v0.z + v0.w + v1.x + v1.y + v1.z + v1.w;
    #pragma unroll
    for (int o = 16; o; o >>= 1) s += __shfl_xor_sync(0xffffffffu, s, o);
    if ((tid & 31) == 0) shs[tid >> 5] = s;
    __syncthreads();
    s = 0.0f;
    #pragma unroll
    for (int i = 0; i < 8; i++) s += shs[i];

    const float inv = 1.0f / s;
    v0.x *= inv; v0.y *= inv; v0.z *= inv; v0.w *= inv;
    v1.x *= inv; v1.y *= inv; v1.z *= inv; v1.w *= inv;

    store_split2(ph + (size_t)tid * 2 + 0, pl + (size_t)tid * 2 + 0, v0.x, v0.y);
    store_split2(ph + (size_t)tid * 2 + 1, pl + (size_t)tid * 2 + 1, v0.z, v0.w);
    store_split2(ph + (size_t)(tid + 256) * 2 + 0, pl + (size_t)(tid + 256) * 2 + 0, v1.x, v1.y);
    store_split2(ph + (size_t)(tid + 256) * 2 + 1, pl + (size_t)(tid + 256) * 2 + 1, v1.z, v1.w);
}

// ---------------------------------------------------------------------------
extern "C" void kernel_launch(void* const* d_in, const int* in_sizes, int n_in,
                              void* d_out, int out_size) {
    const float* Q  = (const float*)d_in[0];   // [B, NQ, DH]
    const float* Kp = (const float*)d_in[1];   // [B, NK, DH]
    float* O = (float*)d_out;                  // [B, NQ, DH]

    float* S; __nv_bfloat16 *qhi, *qlo, *khi, *klo, *kthi, *ktlo, *phi, *plo;
    cudaGetSymbolAddress((void**)&S,    g_S);
    cudaGetSymbolAddress((void**)&qhi,  g_Qhi);
    cudaGetSymbolAddress((void**)&qlo,  g_Qlo);
    cudaGetSymbolAddress((void**)&khi,  g_Khi);
    cudaGetSymbolAddress((void**)&klo,  g_Klo);
    cudaGetSymbolAddress((void**)&kthi, g_Kthi);
    cudaGetSymbolAddress((void**)&ktlo, g_Ktlo);
    cudaGetSymbolAddress((void**)&phi,  g_Phi);
    cudaGetSymbolAddress((void**)&plo,  g_Plo);

    cudaFuncSetAttribute(gemm_mma_kernel, cudaFuncAttributeMaxDynamicSharedMemorySize, GEMM_SMEM);

    const int splitBlocks = (BATCH * NQ * DH) / (256 * 4);   // 8192

    split_kernel<<<splitBlocks, 256>>>(Q, qhi, qlo);
    split_kernel<<<splitBlocks, 256>>>(Kp, khi, klo);
    transpose_split_kernel<<<dim3(NK / 32, DH / 32, BATCH), dim3(32, 8)>>>(Kp, kthi, ktlo);

    // S = Q K^T   (M=2048, N=2048, K=512)
    gemm_mma_kernel<<<dim3(NK / 128, NQ / 128, BATCH), 256, GEMM_SMEM>>>(
        qhi, qlo, khi, klo, S, NQ, NK, DH);

    // P = softmax(S), split to bf16 hi/lo
    softmax_split_kernel<<<BATCH * NQ, 256>>>(S, phi, plo);

    // O = P K     (M=2048, N=512, K=2048), B = K^T (transposed splits, K-major)
    gemm_mma_kernel<<<dim3(DH / 128, NQ / 128, BATCH), 256, GEMM_SMEM>>>(
        phi, plo, kthi, ktlo, O, NQ, DH, NK);
}

// round 10
// speedup vs baseline: 2.0576x; 1.1128x over previous
#include <cuda_runtime.h>
#include <cuda_bf16.h>
#include <math.h>
#include <cstdint>

static constexpr int BATCH = 8;
static constexpr int NQ = 2048;
static constexpr int NK = 2048;
static constexpr int DH = 512;

// ---------------- device scratch (no allocs allowed) ----------------
__device__ float g_S[(size_t)BATCH * NQ * NK];                      // 128 MiB
__device__ __nv_bfloat16 g_Qhi[(size_t)BATCH * NQ * DH];
__device__ __nv_bfloat16 g_Qlo[(size_t)BATCH * NQ * DH];
__device__ __nv_bfloat16 g_Khi[(size_t)BATCH * NK * DH];
__device__ __nv_bfloat16 g_Klo[(size_t)BATCH * NK * DH];
__device__ __nv_bfloat16 g_Kthi[(size_t)BATCH * DH * NK];           // K^T [B, DH, NK]
__device__ __nv_bfloat16 g_Ktlo[(size_t)BATCH * DH * NK];
__device__ __nv_bfloat16 g_Phi[(size_t)BATCH * NQ * NK];            // 64 MiB
__device__ __nv_bfloat16 g_Plo[(size_t)BATCH * NQ * NK];

// ---------------- helpers (sm_80-era PTX only: safe on compute_103) --------
__device__ __forceinline__ uint32_t smem_u32(const void* p) {
    uint32_t a;
    asm("{ .reg .u64 t; cvta.to.shared.u64 t, %1; cvt.u32.u64 %0, t; }" : "=r"(a) : "l"(p));
    return a;
}
__device__ __forceinline__ void cpa16(uint32_t dst, const void* src) {
    asm volatile("cp.async.cg.shared.global [%0], [%1], 16;" :: "r"(dst), "l"(src));
}
__device__ __forceinline__ void cpa_commit() { asm volatile("cp.async.commit_group;" ::: "memory"); }
__device__ __forceinline__ void cpa_wait3()  { asm volatile("cp.async.wait_group 3;" ::: "memory"); }

#define LDSM4(r, addr) \
    asm volatile("ldmatrix.sync.aligned.m8n8.x4.shared.b16 {%0,%1,%2,%3}, [%4];" \
                 : "=r"((r)[0]), "=r"((r)[1]), "=r"((r)[2]), "=r"((r)[3]) : "r"(addr))

#define MMA16816(d, a, b0v, b1v) \
    asm volatile("mma.sync.aligned.m16n8k16.row.col.f32.bf16.bf16.f32 " \
                 "{%0,%1,%2,%3}, {%4,%5,%6,%7}, {%8,%9}, {%0,%1,%2,%3};" \
                 : "+f"((d)[0]), "+f"((d)[1]), "+f"((d)[2]), "+f"((d)[3]) \
                 : "r"((a)[0]), "r"((a)[1]), "r"((a)[2]), "r"((a)[3]), \
                   "r"(b0v), "r"(b1v))

// ---------------------------------------------------------------------------
// Split-bf16 GEMM via mma.sync (HMMA): C[M,N] = (Ahi+Alo) * (Bhi+Blo)^T
// A row-major [M,K] (K contig), B row-major [N,K] (K contig), fp32 out.
// Emulation: hi*hi + lo*hi + hi*lo as a virtual K loop over 3 phases.
// 128x128 tile/CTA, 256 threads, BK=32, 5-stage cp.async ring,
// ONE __syncthreads per chunk. SMEM rows padded to 80B (conflict-free ldmatrix).
// ---------------------------------------------------------------------------
static constexpr int ROWB = 80;                   // bytes per smem row
static constexpr int BTILE = 128 * ROWB;          // 10240 B per operand tile
static constexpr int STAGE = 2 * BTILE;           // A + B per stage (20480 B)
static constexpr int STAGES = 5;
static constexpr int GEMM_SMEM = STAGES * STAGE;  // 102400 B

__global__ __launch_bounds__(256, 2)
void gemm_mma_kernel(const __nv_bfloat16* __restrict__ Ahi, const __nv_bfloat16* __restrict__ Alo,
                     const __nv_bfloat16* __restrict__ Bhi, const __nv_bfloat16* __restrict__ Blo,
                     float* __restrict__ C, int M, int N, int K)
{
    extern __shared__ char smem[];
    const uint32_t sb = smem_u32(smem);
    const int tid = threadIdx.x;
    const int warp = tid >> 5, lane = tid & 31;
    const int wm = warp >> 2, wn = warp & 3;       // 2 x 4 warp grid
    const int bz = blockIdx.z;
    const int m0 = blockIdx.y * 128, n0 = blockIdx.x * 128;

    const size_t offA = (size_t)bz * M * K + (size_t)m0 * K;
    const size_t offB = (size_t)bz * N * K + (size_t)n0 * K;
    const __nv_bfloat16* Ap[3] = {Ahi + offA, Alo + offA, Ahi + offA};
    const __nv_bfloat16* Bp[3] = {Bhi + offB, Bhi + offB, Blo + offB};

    const int KC = K / 32;         // real-K chunks
    const int NC = 3 * KC;         // virtual chunks (3 split phases)

    const int lr = tid >> 2;       // 0..63  (load row)
    const int ls = tid & 3;        // 0..3   (16B chunk in row)

    auto load_chunk = [&](int c, uint32_t buf) {
        const int ph = c / KC;
        const int kk = (c - ph * KC) * 32;
        const char* ga = (const char*)Ap[ph] + (size_t)kk * 2;
        const char* gb = (const char*)Bp[ph] + (size_t)kk * 2;
        cpa16(buf + lr * ROWB + ls * 16,                 ga + (size_t)lr * K * 2 + ls * 16);
        cpa16(buf + (lr + 64) * ROWB + ls * 16,          ga + (size_t)(lr + 64) * K * 2 + ls * 16);
        cpa16(buf + BTILE + lr * ROWB + ls * 16,         gb + (size_t)lr * K * 2 + ls * 16);
        cpa16(buf + BTILE + (lr + 64) * ROWB + ls * 16,  gb + (size_t)(lr + 64) * K * 2 + ls * 16);
    };

    // Prologue: fill STAGES-1 = 4 slots.
    #pragma unroll
    for (int s = 0; s < STAGES - 1; s++) {
        load_chunk(s, sb + (uint32_t)s * STAGE);
        cpa_commit();
    }

    float acc[4][4][4];
    #pragma unroll
    for (int i = 0; i < 4; i++)
        #pragma unroll
        for (int j = 0; j < 4; j++)
            #pragma unroll
            for (int r = 0; r < 4; r++) acc[i][j][r] = 0.0f;

    // ldmatrix base addresses (per-warp, per-lane): row = (lane&15), +16B for k-half
    const uint32_t aoff = (uint32_t)((wm * 64 + (lane & 15)) * ROWB + (lane >> 4) * 16);
    const uint32_t boff = (uint32_t)(BTILE + (wn * 32 + (lane & 15)) * ROWB + (lane >> 4) * 16);

    int slot = 0;          // = c % STAGES
    int wslot = STAGES - 1;// write slot = (c + STAGES-1) % STAGES
    for (int c = 0; c < NC; c++) {
        const uint32_t bp = sb + (uint32_t)slot * STAGE;
        cpa_wait3();               // chunk c resident (<=3 groups pending)
        __syncthreads();           // also proves slot (c-1)%S fully consumed

        #pragma unroll
        for (int ks = 0; ks < 2; ks++) {
            uint32_t a[4][4];
            #pragma unroll
            for (int mi = 0; mi < 4; mi++)
                LDSM4(a[mi], bp + aoff + mi * 16 * ROWB + ks * 32);
            uint32_t b[2][4];
            #pragma unroll
            for (int nb = 0; nb < 2; nb++)
                LDSM4(b[nb], bp + boff + nb * 16 * ROWB + ks * 32);
            #pragma unroll
            for (int mi = 0; mi < 4; mi++) {
                #pragma unroll
                for (int nb = 0; nb < 2; nb++) {
                    MMA16816(acc[mi][nb * 2 + 0], a[mi], b[nb][0], b[nb][2]);
                    MMA16816(acc[mi][nb * 2 + 1], a[mi], b[nb][1], b[nb][3]);
                }
            }
        }

        // Refill the slot consumed at iteration c-1 (safe after this iter's barrier).
        if (c + STAGES - 1 < NC)
            load_chunk(c + STAGES - 1, sb + (uint32_t)wslot * STAGE);
        cpa_commit();

        slot = (slot + 1 == STAGES) ? 0 : slot + 1;
        wslot = (wslot + 1 == STAGES) ? 0 : wslot + 1;
    }

    // Epilogue: fragment layout m16n8: c0,c1 @ (row, 2*(lane%4)); c2,c3 @ row+8
    float* pC = C + (size_t)bz * M * N + (size_t)(m0 + wm * 64) * N + n0 + wn * 32;
    const int er = lane >> 2, ec = (lane & 3) * 2;
    #pragma unroll
    for (int mi = 0; mi < 4; mi++) {
        #pragma unroll
        for (int ni = 0; ni < 4; ni++) {
            float* d0 = pC + (size_t)(mi * 16 + er) * N + ni * 8 + ec;
            float* d1 = d0 + (size_t)8 * N;
            *(float2*)d0 = make_float2(acc[mi][ni][0], acc[mi][ni][1]);
            *(float2*)d1 = make_float2(acc[mi][ni][2], acc[mi][ni][3]);
        }
    }
}

// ---------------------------------------------------------------------------
// fp32 -> (bf16 hi, bf16 lo) elementwise split; 4 elems/thread
// ---------------------------------------------------------------------------
__global__ __launch_bounds__(256)
void split_kernel(const float* __restrict__ x, __nv_bfloat16* __restrict__ hi,
                  __nv_bfloat16* __restrict__ lo) {
    const size_t i = ((size_t)blockIdx.x * 256 + threadIdx.x) * 4;
    const float4 v = *(const float4*)(x + i);
    __nv_bfloat162 h0, h1, l0, l1;
    h0.x = __float2bfloat16(v.x); h0.y = __float2bfloat16(v.y);
    h1.x = __float2bfloat16(v.z); h1.y = __float2bfloat16(v.w);
    l0.x = __float2bfloat16(v.x - __bfloat162float(h0.x));
    l0.y = __float2bfloat16(v.y - __bfloat162float(h0.y));
    l1.x = __float2bfloat16(v.z - __bfloat162float(h1.x));
    l1.y = __float2bfloat16(v.w - __bfloat162float(h1.y));
    ((__nv_bfloat162*)(hi + i))[0] = h0; ((__nv_bfloat162*)(hi + i))[1] = h1;
    ((__nv_bfloat162*)(lo + i))[0] = l0; ((__nv_bfloat162*)(lo + i))[1] = l1;
}

// ---------------------------------------------------------------------------
// K [B, NK, DH] fp32 -> transposed splits [B, DH, NK] bf16 hi/lo
// ---------------------------------------------------------------------------
__global__ __launch_bounds__(256)
void transpose_split_kernel(const float* __restrict__ Kin,
                            __nv_bfloat16* __restrict__ Thi,
                            __nv_bfloat16* __restrict__ Tlo) {
    __shared__ float tile[32][33];
    const int b = blockIdx.z;
    const int n0 = blockIdx.x * 32, d0 = blockIdx.y * 32;
    const int tx = threadIdx.x, ty = threadIdx.y;   // (32, 8)
    const float* src = Kin + (size_t)b * NK * DH;
    #pragma unroll
    for (int j = 0; j < 32; j += 8)
        tile[ty + j][tx] = src[(size_t)(n0 + ty + j) * DH + d0 + tx];
    __syncthreads();
    __nv_bfloat16* th = Thi + (size_t)b * DH * NK;
    __nv_bfloat16* tl = Tlo + (size_t)b * DH * NK;
    #pragma unroll
    for (int j = 0; j < 32; j += 8) {
        const float v = tile[tx][ty + j];
        const __nv_bfloat16 h = __float2bfloat16(v);
        th[(size_t)(d0 + ty + j) * NK + n0 + tx] = h;
        tl[(size_t)(d0 + ty + j) * NK + n0 + tx] = __float2bfloat16(v - __bfloat162float(h));
    }
}

// ---------------------------------------------------------------------------
// Row softmax over NK, emitting split-bf16 probabilities.
// ---------------------------------------------------------------------------
__device__ __forceinline__ void store_split2(__nv_bfloat162* ph, __nv_bfloat162* pl,
                                             float a, float b) {
    __nv_bfloat162 h, l;
    h.x = __float2bfloat16(a); h.y = __float2bfloat16(b);
    l.x = __float2bfloat16(a - __bfloat162float(h.x));
    l.y = __float2bfloat16(b - __bfloat162float(h.y));
    *ph = h; *pl = l;
}

__global__ __launch_bounds__(256)
void softmax_split_kernel(const float* __restrict__ S,
                          __nv_bfloat16* __restrict__ Phi,
                          __nv_bfloat16* __restrict__ Plo) {
    const float* row = S + (size_t)blockIdx.x * NK;
    __nv_bfloat162* ph = (__nv_bfloat162*)(Phi + (size_t)blockIdx.x * NK);
    __nv_bfloat162* pl = (__nv_bfloat162*)(Plo + (size_t)blockIdx.x * NK);
    const int tid = threadIdx.x;

    float4 v0 = *(const float4*)(row + (size_t)tid * 4);
    float4 v1 = *(const float4*)(row + (size_t)(tid + 256) * 4);

    float mx = fmaxf(fmaxf(fmaxf(v0.x, v0.y), fmaxf(v0.z, v0.w)),
                     fmaxf(fmaxf(v1.x, v1.y), fmaxf(v1.z, v1.w)));

    __shared__ float shm[8];
    __shared__ float shs[8];

    #pragma unroll
    for (int o = 16; o; o >>= 1) mx = fmaxf(mx, __shfl_xor_sync(0xffffffffu, mx, o));
    if ((tid & 31) == 0) shm[tid >> 5] = mx;
    __syncthreads();
    mx = shm[0];
    #pragma unroll
    for (int i = 1; i < 8; i++) mx = fmaxf(mx, shm[i]);

    v0.x = __expf(v0.x - mx); v0.y = __expf(v0.y - mx);
    v0.z = __expf(v0.z - mx); v0.w = __expf(v0.w - mx);
    v1.x = __expf(v1.x - mx); v1.y = __expf(v1.y - mx);
    v1.z = __expf(v1.z - mx); v1.w = __expf(v1.w - mx);

    float s = v0.x + v0.y + v0.z + v0.w + v1.x + v1.y + v1.z + v1.w;
    #pragma unroll
    for (int o = 16; o; o >>= 1) s += __shfl_xor_sync(0xffffffffu, s, o);
    if ((tid & 31) == 0) shs[tid >> 5] = s;
    __syncthreads();
    s = 0.0f;
    #pragma unroll
    for (int i = 0; i < 8; i++) s += shs[i];

    const float inv = 1.0f / s;
    v0.x *= inv; v0.y *= inv; v0.z *= inv; v0.w *= inv;
    v1.x *= inv; v1.y *= inv; v1.z *= inv; v1.w *= inv;

    store_split2(ph + (size_t)tid * 2 + 0, pl + (size_t)tid * 2 + 0, v0.x, v0.y);
    store_split2(ph + (size_t)tid * 2 + 1, pl + (size_t)tid * 2 + 1, v0.z, v0.w);
    store_split2(ph + (size_t)(tid + 256) * 2 + 0, pl + (size_t)(tid + 256) * 2 + 0, v1.x, v1.y);
    store_split2(ph + (size_t)(tid + 256) * 2 + 1, pl + (size_t)(tid + 256) * 2 + 1, v1.z, v1.w);
}

// ---------------------------------------------------------------------------
extern "C" void kernel_launch(void* const* d_in, const int* in_sizes, int n_in,
                              void* d_out, int out_size) {
    const float* Q  = (const float*)d_in[0];   // [B, NQ, DH]
    const float* Kp = (const float*)d_in[1];   // [B, NK, DH]
    float* O = (float*)d_out;                  // [B, NQ, DH]

    float* S; __nv_bfloat16 *qhi, *qlo, *khi, *klo, *kthi, *ktlo, *phi, *plo;
    cudaGetSymbolAddress((void**)&S,    g_S);
    cudaGetSymbolAddress((void**)&qhi,  g_Qhi);
    cudaGetSymbolAddress((void**)&qlo,  g_Qlo);
    cudaGetSymbolAddress((void**)&khi,  g_Khi);
    cudaGetSymbolAddress((void**)&klo,  g_Klo);
    cudaGetSymbolAddress((void**)&kthi, g_Kthi);
    cudaGetSymbolAddress((void**)&ktlo, g_Ktlo);
    cudaGetSymbolAddress((void**)&phi,  g_Phi);
    cudaGetSymbolAddress((void**)&plo,  g_Plo);

    cudaFuncSetAttribute(gemm_mma_kernel, cudaFuncAttributeMaxDynamicSharedMemorySize, GEMM_SMEM);

    const int splitBlocks = (BATCH * NQ * DH) / (256 * 4);   // 8192

    split_kernel<<<splitBlocks, 256>>>(Q, qhi, qlo);
    split_kernel<<<splitBlocks, 256>>>(Kp, khi, klo);
    transpose_split_kernel<<<dim3(NK / 32, DH / 32, BATCH), dim3(32, 8)>>>(Kp, kthi, ktlo);

    // S = Q K^T   (M=2048, N=2048, K=512)
    gemm_mma_kernel<<<dim3(NK / 128, NQ / 128, BATCH), 256, GEMM_SMEM>>>(
        qhi, qlo, khi, klo, S, NQ, NK, DH);

    // P = softmax(S), split to bf16 hi/lo
    softmax_split_kernel<<<BATCH * NQ, 256>>>(S, phi, plo);

    // O = P K     (M=2048, N=512, K=2048), B = K^T (transposed splits, K-major)
    gemm_mma_kernel<<<dim3(DH / 128, NQ / 128, BATCH), 256, GEMM_SMEM>>>(
        phi, plo, kthi, ktlo, O, NQ, DH, NK);
}

// round 11
// speedup vs baseline: 2.2786x; 1.1074x over previous
#include <cuda_runtime.h>
#include <cuda_bf16.h>
#include <math.h>
#include <cstdint>

static constexpr int BATCH = 8;
static constexpr int NQ = 2048;
static constexpr int NK = 2048;
static constexpr int DH = 512;

// ---------------- device scratch (no allocs allowed) ----------------
__device__ float g_S[(size_t)BATCH * NQ * NK];                      // 128 MiB
__device__ __nv_bfloat16 g_Qhi[(size_t)BATCH * NQ * DH];
__device__ __nv_bfloat16 g_Qlo[(size_t)BATCH * NQ * DH];
__device__ __nv_bfloat16 g_Khi[(size_t)BATCH * NK * DH];
__device__ __nv_bfloat16 g_Klo[(size_t)BATCH * NK * DH];
__device__ __nv_bfloat16 g_Kthi[(size_t)BATCH * DH * NK];           // K^T [B, DH, NK]
__device__ __nv_bfloat16 g_Ktlo[(size_t)BATCH * DH * NK];
__device__ __nv_bfloat16 g_Phi[(size_t)BATCH * NQ * NK];            // 64 MiB
__device__ __nv_bfloat16 g_Plo[(size_t)BATCH * NQ * NK];

// ---------------- helpers (sm_80-era PTX only: safe on compute_103) --------
__device__ __forceinline__ uint32_t smem_u32(const void* p) {
    uint32_t a;
    asm("{ .reg .u64 t; cvta.to.shared.u64 t, %1; cvt.u32.u64 %0, t; }" : "=r"(a) : "l"(p));
    return a;
}
__device__ __forceinline__ void cpa16(uint32_t dst, const void* src) {
    asm volatile("cp.async.cg.shared.global [%0], [%1], 16;" :: "r"(dst), "l"(src));
}
__device__ __forceinline__ void cpa_commit() { asm volatile("cp.async.commit_group;" ::: "memory"); }
__device__ __forceinline__ void cpa_wait1()  { asm volatile("cp.async.wait_group 1;" ::: "memory"); }

#define LDSM4(r, addr) \
    asm volatile("ldmatrix.sync.aligned.m8n8.x4.shared.b16 {%0,%1,%2,%3}, [%4];" \
                 : "=r"((r)[0]), "=r"((r)[1]), "=r"((r)[2]), "=r"((r)[3]) : "r"(addr))

#define MMA16816(d, a, b0v, b1v) \
    asm volatile("mma.sync.aligned.m16n8k16.row.col.f32.bf16.bf16.f32 " \
                 "{%0,%1,%2,%3}, {%4,%5,%6,%7}, {%8,%9}, {%0,%1,%2,%3};" \
                 : "+f"((d)[0]), "+f"((d)[1]), "+f"((d)[2]), "+f"((d)[3]) \
                 : "r"((a)[0]), "r"((a)[1]), "r"((a)[2]), "r"((a)[3]), \
                   "r"(b0v), "r"(b1v))

// ---------------------------------------------------------------------------
// Split-bf16 GEMM via mma.sync: C = (Ahi+Alo)*(Bhi+Blo)^T, dropping lo*lo.
// All 3 products (hh, lh, hl) computed while the K-chunk tiles are resident:
// one smem stage holds Ahi|Alo|Bhi|Blo (4 x 10240B). 2-stage ring, BK=32.
// 128x128 tile/CTA, 256 threads, 2x4 warp grid (64x32 warp tiles).
// SMEM rows padded to 80B -> conflict-free ldmatrix.
// ---------------------------------------------------------------------------
static constexpr int ROWB = 80;                   // bytes per smem row
static constexpr int BTILE = 128 * ROWB;          // 10240 B per operand tile
static constexpr int STAGE = 4 * BTILE;           // Ahi+Alo+Bhi+Blo (40960 B)
static constexpr int STAGES = 2;
static constexpr int GEMM_SMEM = STAGES * STAGE;  // 81920 B

__global__ __launch_bounds__(256, 2)
void gemm_mma_kernel(const __nv_bfloat16* __restrict__ Ahi, const __nv_bfloat16* __restrict__ Alo,
                     const __nv_bfloat16* __restrict__ Bhi, const __nv_bfloat16* __restrict__ Blo,
                     float* __restrict__ C, int M, int N, int K)
{
    extern __shared__ char smem[];
    const uint32_t sb = smem_u32(smem);
    const int tid = threadIdx.x;
    const int warp = tid >> 5, lane = tid & 31;
    const int wm = warp >> 2, wn = warp & 3;       // 2 x 4 warp grid
    const int bz = blockIdx.z;
    const int m0 = blockIdx.y * 128, n0 = blockIdx.x * 128;

    const size_t offA = (size_t)bz * M * K + (size_t)m0 * K;
    const size_t offB = (size_t)bz * N * K + (size_t)n0 * K;
    const __nv_bfloat16* gAhi = Ahi + offA;
    const __nv_bfloat16* gAlo = Alo + offA;
    const __nv_bfloat16* gBhi = Bhi + offB;
    const __nv_bfloat16* gBlo = Blo + offB;

    const int KC = K / 32;         // K-chunks

    const int lr = tid >> 2;       // 0..63  (load row)
    const int ls = tid & 3;        // 0..3   (16B chunk within 64B row)

    // Load one K-chunk: 4 tiles (Ahi, Alo, Bhi, Blo), 8 cp.async per thread.
    auto load_chunk = [&](int c, uint32_t buf) {
        const size_t kb = (size_t)c * 64;          // byte offset along K
        const char* t0 = (const char*)gAhi + kb;
        const char* t1 = (const char*)gAlo + kb;
        const char* t2 = (const char*)gBhi + kb;
        const char* t3 = (const char*)gBlo + kb;
        const uint32_t so = lr * ROWB + ls * 16;
        const uint32_t so2 = (lr + 64) * ROWB + ls * 16;
        const size_t go = (size_t)lr * K * 2 + ls * 16;
        const size_t go2 = (size_t)(lr + 64) * K * 2 + ls * 16;
        cpa16(buf + so,              t0 + go);
        cpa16(buf + so2,             t0 + go2);
        cpa16(buf + BTILE + so,      t1 + go);
        cpa16(buf + BTILE + so2,     t1 + go2);
        cpa16(buf + 2 * BTILE + so,  t2 + go);
        cpa16(buf + 2 * BTILE + so2, t2 + go2);
        cpa16(buf + 3 * BTILE + so,  t3 + go);
        cpa16(buf + 3 * BTILE + so2, t3 + go2);
    };

    load_chunk(0, sb);          cpa_commit();
    load_chunk(1, sb + STAGE);  cpa_commit();

    float acc[4][4][4];
    #pragma unroll
    for (int i = 0; i < 4; i++)
        #pragma unroll
        for (int j = 0; j < 4; j++)
            #pragma unroll
            for (int r = 0; r < 4; r++) acc[i][j][r] = 0.0f;

    // ldmatrix per-lane base offsets within a tile
    const uint32_t aoff = (uint32_t)((wm * 64 + (lane & 15)) * ROWB + (lane >> 4) * 16);
    const uint32_t boff = (uint32_t)((wn * 32 + (lane & 15)) * ROWB + (lane >> 4) * 16);

    for (int c = 0; c < KC; c++) {
        const uint32_t bp = sb + (uint32_t)(c & 1) * STAGE;
        cpa_wait1();
        __syncthreads();

        #pragma unroll
        for (int ks = 0; ks < 2; ks++) {
            const uint32_t ko = (uint32_t)(ks * 32);
            uint32_t ah[4][4], bh[2][4];
            #pragma unroll
            for (int mi = 0; mi < 4; mi++)
                LDSM4(ah[mi], bp + aoff + mi * 16 * ROWB + ko);
            #pragma unroll
            for (int nb = 0; nb < 2; nb++)
                LDSM4(bh[nb], bp + 2 * BTILE + boff + nb * 16 * ROWB + ko);

            // hi * hi
            #pragma unroll
            for (int mi = 0; mi < 4; mi++)
                #pragma unroll
                for (int nb = 0; nb < 2; nb++) {
                    MMA16816(acc[mi][nb * 2 + 0], ah[mi], bh[nb][0], bh[nb][2]);
                    MMA16816(acc[mi][nb * 2 + 1], ah[mi], bh[nb][1], bh[nb][3]);
                }
            // lo * hi  (reuse bh; al scoped to keep peak registers low)
            {
                uint32_t al[4][4];
                #pragma unroll
                for (int mi = 0; mi < 4; mi++)
                    LDSM4(al[mi], bp + BTILE + aoff + mi * 16 * ROWB + ko);
                #pragma unroll
                for (int mi = 0; mi < 4; mi++)
                    #pragma unroll
                    for (int nb = 0; nb < 2; nb++) {
                        MMA16816(acc[mi][nb * 2 + 0], al[mi], bh[nb][0], bh[nb][2]);
                        MMA16816(acc[mi][nb * 2 + 1], al[mi], bh[nb][1], bh[nb][3]);
                    }
            }
            // hi * lo  (reuse ah)
            {
                uint32_t bl[2][4];
                #pragma unroll
                for (int nb = 0; nb < 2; nb++)
                    LDSM4(bl[nb], bp + 3 * BTILE + boff + nb * 16 * ROWB + ko);
                #pragma unroll
                for (int mi = 0; mi < 4; mi++)
                    #pragma unroll
                    for (int nb = 0; nb < 2; nb++) {
                        MMA16816(acc[mi][nb * 2 + 0], ah[mi], bl[nb][0], bl[nb][2]);
                        MMA16816(acc[mi][nb * 2 + 1], ah[mi], bl[nb][1], bl[nb][3]);
                    }
            }
        }

        __syncthreads();           // all warps done reading this slot
        if (c + 2 < KC) load_chunk(c + 2, bp);
        cpa_commit();
    }

    // Epilogue: fragment layout m16n8: c0,c1 @ (row, 2*(lane%4)); c2,c3 @ row+8
    float* pC = C + (size_t)bz * M * N + (size_t)(m0 + wm * 64) * N + n0 + wn * 32;
    const int er = lane >> 2, ec = (lane & 3) * 2;
    #pragma unroll
    for (int mi = 0; mi < 4; mi++) {
        #pragma unroll
        for (int ni = 0; ni < 4; ni++) {
            float* d0 = pC + (size_t)(mi * 16 + er) * N + ni * 8 + ec;
            float* d1 = d0 + (size_t)8 * N;
            *(float2*)d0 = make_float2(acc[mi][ni][0], acc[mi][ni][1]);
            *(float2*)d1 = make_float2(acc[mi][ni][2], acc[mi][ni][3]);
        }
    }
}

// ---------------------------------------------------------------------------
// fp32 -> (bf16 hi, bf16 lo) elementwise split; 4 elems/thread
// ---------------------------------------------------------------------------
__global__ __launch_bounds__(256)
void split_kernel(const float* __restrict__ x, __nv_bfloat16* __restrict__ hi,
                  __nv_bfloat16* __restrict__ lo) {
    const size_t i = ((size_t)blockIdx.x * 256 + threadIdx.x) * 4;
    const float4 v = *(const float4*)(x + i);
    __nv_bfloat162 h0, h1, l0, l1;
    h0.x = __float2bfloat16(v.x); h0.y = __float2bfloat16(v.y);
    h1.x = __float2bfloat16(v.z); h1.y = __float2bfloat16(v.w);
    l0.x = __float2bfloat16(v.x - __bfloat162float(h0.x));
    l0.y = __float2bfloat16(v.y - __bfloat162float(h0.y));
    l1.x = __float2bfloat16(v.z - __bfloat162float(h1.x));
    l1.y = __float2bfloat16(v.w - __bfloat162float(h1.y));
    ((__nv_bfloat162*)(hi + i))[0] = h0; ((__nv_bfloat162*)(hi + i))[1] = h1;
    ((__nv_bfloat162*)(lo + i))[0] = l0; ((__nv_bfloat162*)(lo + i))[1] = l1;
}

// ---------------------------------------------------------------------------
// K [B, NK, DH] fp32 -> transposed splits [B, DH, NK] bf16 hi/lo
// ---------------------------------------------------------------------------
__global__ __launch_bounds__(256)
void transpose_split_kernel(const float* __restrict__ Kin,
                            __nv_bfloat16* __restrict__ Thi,
                            __nv_bfloat16* __restrict__ Tlo) {
    __shared__ float tile[32][33];
    const int b = blockIdx.z;
    const int n0 = blockIdx.x * 32, d0 = blockIdx.y * 32;
    const int tx = threadIdx.x, ty = threadIdx.y;   // (32, 8)
    const float* src = Kin + (size_t)b * NK * DH;
    #pragma unroll
    for (int j = 0; j < 32; j += 8)
        tile[ty + j][tx] = src[(size_t)(n0 + ty + j) * DH + d0 + tx];
    __syncthreads();
    __nv_bfloat16* th = Thi + (size_t)b * DH * NK;
    __nv_bfloat16* tl = Tlo + (size_t)b * DH * NK;
    #pragma unroll
    for (int j = 0; j < 32; j += 8) {
        const float v = tile[tx][ty + j];
        const __nv_bfloat16 h = __float2bfloat16(v);
        th[(size_t)(d0 + ty + j) * NK + n0 + tx] = h;
        tl[(size_t)(d0 + ty + j) * NK + n0 + tx] = __float2bfloat16(v - __bfloat162float(h));
    }
}

// ---------------------------------------------------------------------------
// Row softmax over NK, emitting split-bf16 probabilities.
// ---------------------------------------------------------------------------
__device__ __forceinline__ void store_split2(__nv_bfloat162* ph, __nv_bfloat162* pl,
                                             float a, float b) {
    __nv_bfloat162 h, l;
    h.x = __float2bfloat16(a); h.y = __float2bfloat16(b);
    l.x = __float2bfloat16(a - __bfloat162float(h.x));
    l.y = __float2bfloat16(b - __bfloat162float(h.y));
    *ph = h; *pl = l;
}

__global__ __launch_bounds__(256)
void softmax_split_kernel(const float* __restrict__ S,
                          __nv_bfloat16* __restrict__ Phi,
                          __nv_bfloat16* __restrict__ Plo) {
    const float* row = S + (size_t)blockIdx.x * NK;
    __nv_bfloat162* ph = (__nv_bfloat162*)(Phi + (size_t)blockIdx.x * NK);
    __nv_bfloat162* pl = (__nv_bfloat162*)(Plo + (size_t)blockIdx.x * NK);
    const int tid = threadIdx.x;

    float4 v0 = *(const float4*)(row + (size_t)tid * 4);
    float4 v1 = *(const float4*)(row + (size_t)(tid + 256) * 4);

    float mx = fmaxf(fmaxf(fmaxf(v0.x, v0.y), fmaxf(v0.z, v0.w)),
                     fmaxf(fmaxf(v1.x, v1.y), fmaxf(v1.z, v1.w)));

    __shared__ float shm[8];
    __shared__ float shs[8];

    #pragma unroll
    for (int o = 16; o; o >>= 1) mx = fmaxf(mx, __shfl_xor_sync(0xffffffffu, mx, o));
    if ((tid & 31) == 0) shm[tid >> 5] = mx;
    __syncthreads();
    mx = shm[0];
    #pragma unroll
    for (int i = 1; i < 8; i++) mx = fmaxf(mx, shm[i]);

    v0.x = __expf(v0.x - mx); v0.y = __expf(v0.y - mx);
    v0.z = __expf(v0.z - mx); v0.w = __expf(v0.w - mx);
    v1.x = __expf(v1.x - mx); v1.y = __expf(v1.y - mx);
    v1.z = __expf(v1.z - mx); v1.w = __expf(v1.w - mx);

    float s = v0.x + v0.y + v0.z + v0.w + v1.x + v1.y + v1.z + v1.w;
    #pragma unroll
    for (int o = 16; o; o >>= 1) s += __shfl_xor_sync(0xffffffffu, s, o);
    if ((tid & 31) == 0) shs[tid >> 5] = s;
    __syncthreads();
    s = 0.0f;
    #pragma unroll
    for (int i = 0; i < 8; i++) s += shs[i];

    const float inv = 1.0f / s;
    v0.x *= inv; v0.y *= inv; v0.z *= inv; v0.w *= inv;
    v1.x *= inv; v1.y *= inv; v1.z *= inv; v1.w *= inv;

    store_split2(ph + (size_t)tid * 2 + 0, pl + (size_t)tid * 2 + 0, v0.x, v0.y);
    store_split2(ph + (size_t)tid * 2 + 1, pl + (size_t)tid * 2 + 1, v0.z, v0.w);
    store_split2(ph + (size_t)(tid + 256) * 2 + 0, pl + (size_t)(tid + 256) * 2 + 0, v1.x, v1.y);
    store_split2(ph + (size_t)(tid + 256) * 2 + 1, pl + (size_t)(tid + 256) * 2 + 1, v1.z, v1.w);
}

// ---------------------------------------------------------------------------
extern "C" void kernel_launch(void* const* d_in, const int* in_sizes, int n_in,
                              void* d_out, int out_size) {
    const float* Q  = (const float*)d_in[0];   // [B, NQ, DH]
    const float* Kp = (const float*)d_in[1];   // [B, NK, DH]
    float* O = (float*)d_out;                  // [B, NQ, DH]

    float* S; __nv_bfloat16 *qhi, *qlo, *khi, *klo, *kthi, *ktlo, *phi, *plo;
    cudaGetSymbolAddress((void**)&S,    g_S);
    cudaGetSymbolAddress((void**)&qhi,  g_Qhi);
    cudaGetSymbolAddress((void**)&qlo,  g_Qlo);
    cudaGetSymbolAddress((void**)&khi,  g_Khi);
    cudaGetSymbolAddress((void**)&klo,  g_Klo);
    cudaGetSymbolAddress((void**)&kthi, g_Kthi);
    cudaGetSymbolAddress((void**)&ktlo, g_Ktlo);
    cudaGetSymbolAddress((void**)&phi,  g_Phi);
    cudaGetSymbolAddress((void**)&plo,  g_Plo);

    cudaFuncSetAttribute(gemm_mma_kernel, cudaFuncAttributeMaxDynamicSharedMemorySize, GEMM_SMEM);

    const int splitBlocks = (BATCH * NQ * DH) / (256 * 4);   // 8192

    split_kernel<<<splitBlocks, 256>>>(Q, qhi, qlo);
    split_kernel<<<splitBlocks, 256>>>(Kp, khi, klo);
    transpose_split_kernel<<<dim3(NK / 32, DH / 32, BATCH), dim3(32, 8)>>>(Kp, kthi, ktlo);

    // S = Q K^T   (M=2048, N=2048, K=512)
    gemm_mma_kernel<<<dim3(NK / 128, NQ / 128, BATCH), 256, GEMM_SMEM>>>(
        qhi, qlo, khi, klo, S, NQ, NK, DH);

    // P = softmax(S), split to bf16 hi/lo
    softmax_split_kernel<<<BATCH * NQ, 256>>>(S, phi, plo);

    // O = P K     (M=2048, N=512, K=2048), B = K^T (transposed splits, K-major)
    gemm_mma_kernel<<<dim3(DH / 128, NQ / 128, BATCH), 256, GEMM_SMEM>>>(
        phi, plo, kthi, ktlo, O, NQ, DH, NK);
}